// round 1
// baseline (speedup 1.0000x reference)
#include <cuda_runtime.h>
#include <cuda_bf16.h>

// Problem constants (fixed by the dataset)
#define NN 50000
#define EE 1000000
#define C 64

// ---------------- static scratch (no allocations allowed) ----------------
__device__ float g_hw[NN * C];   // h = x @ W (pre-softmax features of current layer)
__device__ float g_h[NN * C];    // layer output (post relu)
__device__ float g_acc[NN * C];  // segment-sum accumulator (unnormalized)
__device__ float g_A[NN * C];    // h2 @ Wm1[0:64]
__device__ float g_B[NN * C];    // h2 @ Wm1[65:129]
__device__ float g_al[NN];
__device__ float g_ar[NN];
__device__ float g_s[NN];        // softmax denominators
__device__ int   g_src[EE];
__device__ int   g_dst[EE];
__device__ int   g_i32flag;      // nonzero => edge_index is int32

// ---------------- edge_index dtype detect + convert ----------------
__global__ void reset_flag_kernel() { g_i32flag = 0; }

// Read the first 2M 32-bit words (safe for both int32 [8MB] and int64 [16MB]).
// If underlying data is int64 (values < 2^31), every odd word is 0.
__global__ void detect_kernel(const int* __restrict__ w, int nwords_half) {
    int t = blockIdx.x * blockDim.x + threadIdx.x;
    if (t >= nwords_half) return;
    if (w[2 * t + 1] != 0) atomicOr(&g_i32flag, 1);
}

__global__ void conv_idx_kernel(const void* __restrict__ ei, int E) {
    int e = blockIdx.x * blockDim.x + threadIdx.x;
    if (e >= E) return;
    if (g_i32flag == 0) {
        const long long* p = (const long long*)ei;
        g_src[e] = (int)p[e];
        g_dst[e] = (int)p[(size_t)E + e];
    } else {
        const int* p = (const int*)ei;
        g_src[e] = p[e];
        g_dst[e] = p[E + e];
    }
}

// ---------------- 64x64 GEMM: Y = X @ W  (row-major) ----------------
// inSel: 0 -> X = Xext, 1 -> X = g_h
// outSel: 0 -> g_hw, 1 -> g_A, 2 -> g_B
__global__ __launch_bounds__(256) void gemm64_kernel(
    const float* __restrict__ Xext, const float* __restrict__ W,
    int inSel, int outSel, int n)
{
    __shared__ float Ws[C * C];   // 16 KB
    __shared__ float Xs[16 * C];  // 4 KB
    const float* X = inSel ? g_h : Xext;
    float* Y = (outSel == 0) ? g_hw : ((outSel == 1) ? g_A : g_B);

    int tid = threadIdx.x;
    for (int i = tid; i < C * C; i += 256) Ws[i] = W[i];
    int row0 = blockIdx.x * 16;
    for (int i = tid; i < 16 * C; i += 256) {
        int r = row0 + (i >> 6);
        Xs[i] = (r < n) ? X[(size_t)r * C + (i & 63)] : 0.f;
    }
    __syncthreads();

    int c = tid & 63;
    int rg = tid >> 6;  // 0..3
    #pragma unroll
    for (int rr = 0; rr < 4; rr++) {
        int rl = rg * 4 + rr;
        int r = row0 + rl;
        if (r >= n) break;
        float sum = 0.f;
        #pragma unroll
        for (int k = 0; k < C; k++) sum += Xs[rl * C + k] * Ws[k * C + c];
        Y[(size_t)r * C + c] = sum;
    }
}

// ---------------- per-node: al/ar dots + self-loop init of s/acc ----------------
__global__ __launch_bounds__(256) void self_kernel(
    const float* __restrict__ attL, const float* __restrict__ attR, int n)
{
    int node = (blockIdx.x * blockDim.x + threadIdx.x) >> 5;
    int lane = threadIdx.x & 31;
    if (node >= n) return;
    float2 h = ((const float2*)(g_hw + (size_t)node * C))[lane];
    float2 aL = ((const float2*)attL)[lane];
    float2 aR = ((const float2*)attR)[lane];
    float dl = h.x * aL.x + h.y * aL.y;
    float dr = h.x * aR.x + h.y * aR.y;
    float dd = h.x * h.x + h.y * h.y;
    #pragma unroll
    for (int o = 16; o; o >>= 1) {
        dl += __shfl_xor_sync(0xffffffffu, dl, o);
        dr += __shfl_xor_sync(0xffffffffu, dr, o);
        dd += __shfl_xor_sync(0xffffffffu, dd, o);
    }
    float a = (dl + dr) / (1.f + __expf(-dd));  // * sigmoid(logit)
    a = (a > 0.f) ? a : 0.2f * a;               // leaky relu
    float ex = __expf(a);
    if (lane == 0) { g_al[node] = dl; g_ar[node] = dr; g_s[node] = ex; }
    ((float2*)(g_acc + (size_t)node * C))[lane] = make_float2(h.x * ex, h.y * ex);
}

// ---------------- fused attention + aggregation edge pass ----------------
__global__ __launch_bounds__(256) void edge_kernel(int E)
{
    int e = (blockIdx.x * blockDim.x + threadIdx.x) >> 5;
    int lane = threadIdx.x & 31;
    if (e >= E) return;
    int j = __ldg(g_src + e);  // source
    int i = __ldg(g_dst + e);  // target (softmax group)
    float2 hj = ((const float2*)(g_hw + (size_t)j * C))[lane];
    float2 hi = ((const float2*)(g_hw + (size_t)i * C))[lane];
    float d = hj.x * hi.x + hj.y * hi.y;
    #pragma unroll
    for (int o = 16; o; o >>= 1) d += __shfl_xor_sync(0xffffffffu, d, o);
    float a = (__ldg(g_al + j) + __ldg(g_ar + i)) / (1.f + __expf(-d));
    a = (a > 0.f) ? a : 0.2f * a;
    float ex = __expf(a);
    float* ap = g_acc + (size_t)i * C + lane * 2;
    atomicAdd(ap, hj.x * ex);
    atomicAdd(ap + 1, hj.y * ex);
    if (lane == 0) atomicAdd(g_s + i, ex);
}

// ---------------- normalize + bias + relu -> g_h ----------------
__global__ __launch_bounds__(256) void finalize_kernel(
    const float* __restrict__ bias, int n)
{
    int idx = blockIdx.x * blockDim.x + threadIdx.x;
    if (idx >= n * C) return;
    int node = idx >> 6, c = idx & 63;
    float v = g_acc[idx] / g_s[node] + __ldg(bias + c);
    g_h[idx] = (v > 0.f) ? v : 0.f;
}

// ---------------- edge MLP: out[e] = relu(A[src]+B[dst]+ea*Wrow+bm1) @ Wm2 + bm2 --------
__global__ __launch_bounds__(256) void mlp_edge_kernel(
    const float* __restrict__ edge_attr,
    const float* __restrict__ Wm1row64,   // Wm1 + 64*64
    const float* __restrict__ bm1,
    const float* __restrict__ Wm2,
    const float* __restrict__ bm2,
    float* __restrict__ out, int E)
{
    int e = (blockIdx.x * blockDim.x + threadIdx.x) >> 5;
    int lane = threadIdx.x & 31;
    if (e >= E) return;
    int j = __ldg(g_src + e);
    int i = __ldg(g_dst + e);
    float ea = __ldg(edge_attr + e);
    float2 a  = ((const float2*)(g_A + (size_t)j * C))[lane];
    float2 b  = ((const float2*)(g_B + (size_t)i * C))[lane];
    float2 we = ((const float2*)Wm1row64)[lane];
    float2 bb = ((const float2*)bm1)[lane];
    float2 w2 = ((const float2*)Wm2)[lane];
    float tx = a.x + b.x + ea * we.x + bb.x; tx = (tx > 0.f) ? tx : 0.f;
    float ty = a.y + b.y + ea * we.y + bb.y; ty = (ty > 0.f) ? ty : 0.f;
    float d = tx * w2.x + ty * w2.y;
    #pragma unroll
    for (int o = 16; o; o >>= 1) d += __shfl_xor_sync(0xffffffffu, d, o);
    if (lane == 0) out[e] = d + __ldg(bm2);
}

// ---------------- launcher ----------------
extern "C" void kernel_launch(void* const* d_in, const int* in_sizes, int n_in,
                              void* d_out, int out_size)
{
    const float* x     = (const float*)d_in[0];
    const void*  ei    = d_in[1];
    const float* ea    = (const float*)d_in[2];
    const float* W1    = (const float*)d_in[3];
    const float* attL1 = (const float*)d_in[4];
    const float* attR1 = (const float*)d_in[5];
    const float* b1    = (const float*)d_in[6];
    const float* W2    = (const float*)d_in[7];
    const float* attL2 = (const float*)d_in[8];
    const float* attR2 = (const float*)d_in[9];
    const float* b2    = (const float*)d_in[10];
    const float* Wm1   = (const float*)d_in[11];
    const float* bm1   = (const float*)d_in[12];
    const float* Wm2   = (const float*)d_in[13];
    const float* bm2   = (const float*)d_in[14];
    float* out = (float*)d_out;

    int n = in_sizes[0] / C;     // 50000
    int E = in_sizes[2];         // edge_attr is [E,1] -> E elements

    const int TB = 256;
    int gemmGrid  = (n + 15) / 16;
    int nodeWarps = (n * 32 + TB - 1) / TB;
    int edgeWarps = ((size_t)E * 32 + TB - 1) / TB;
    int finGrid   = (n * C + TB - 1) / TB;

    // 0) edge index dtype detect + convert to int32
    reset_flag_kernel<<<1, 1>>>();
    {
        int half = E;  // check E odd words within the first 2E 32-bit words (safe both ways)
        detect_kernel<<<(half + TB - 1) / TB, TB>>>((const int*)ei, half);
    }
    conv_idx_kernel<<<(E + TB - 1) / TB, TB>>>(ei, E);

    // ---- Layer 1 ----
    gemm64_kernel<<<gemmGrid, TB>>>(x, W1, /*inSel=*/0, /*outSel=*/0, n);
    self_kernel<<<nodeWarps, TB>>>(attL1, attR1, n);
    edge_kernel<<<edgeWarps, TB>>>(E);
    finalize_kernel<<<finGrid, TB>>>(b1, n);

    // ---- Layer 2 ----
    gemm64_kernel<<<gemmGrid, TB>>>(nullptr, W2, /*inSel=*/1, /*outSel=*/0, n);
    self_kernel<<<nodeWarps, TB>>>(attL2, attR2, n);
    edge_kernel<<<edgeWarps, TB>>>(E);
    finalize_kernel<<<finGrid, TB>>>(b2, n);

    // ---- Edge MLP ----
    gemm64_kernel<<<gemmGrid, TB>>>(nullptr, Wm1,            /*inSel=*/1, /*outSel=*/1, n);  // A = h2 @ Wm1[0:64]
    gemm64_kernel<<<gemmGrid, TB>>>(nullptr, Wm1 + 65 * C,   /*inSel=*/1, /*outSel=*/2, n);  // B = h2 @ Wm1[65:129]
    mlp_edge_kernel<<<edgeWarps, TB>>>(ea, Wm1 + 64 * C, bm1, Wm2, bm2, out, E);
}

// round 2
// speedup vs baseline: 1.6047x; 1.6047x over previous
#include <cuda_runtime.h>
#include <cuda_bf16.h>

#define NN 50000
#define EE 1000000
#define C 64

// ---------------- static scratch ----------------
__device__ float g_hw[NN * C];   // h = x @ W (pre-softmax features)
__device__ float g_h[NN * C];    // layer output (post relu)
__device__ float g_acc[NN * C];  // segment-sum accumulator
__device__ float g_A[NN * C];    // h2 @ Wm1[0:64]
__device__ float g_B[NN * C];    // h2 @ Wm1[65:129]
__device__ float g_al[NN];
__device__ float g_ar[NN];
__device__ float g_s[NN];
__device__ int   g_src[EE];
__device__ int   g_dst[EE];
__device__ int   g_i32flag;

// ---------------- edge_index dtype detect + convert ----------------
__global__ void reset_flag_kernel() { g_i32flag = 0; }

__global__ void detect_kernel(const int* __restrict__ w, int nwords_half) {
    int t = blockIdx.x * blockDim.x + threadIdx.x;
    if (t >= nwords_half) return;
    if (w[2 * t + 1] != 0) atomicOr(&g_i32flag, 1);
}

__global__ void conv_idx_kernel(const void* __restrict__ ei, int E) {
    int e = blockIdx.x * blockDim.x + threadIdx.x;
    if (e >= E) return;
    if (g_i32flag == 0) {
        const long long* p = (const long long*)ei;
        g_src[e] = (int)p[e];
        g_dst[e] = (int)p[(size_t)E + e];
    } else {
        const int* p = (const int*)ei;
        g_src[e] = p[e];
        g_dst[e] = p[E + e];
    }
}

// ---------------- 64x64 GEMM: Y = X @ W, register-blocked ----------------
// Block: 64 rows x 64 cols, 256 threads (16x16), 4x4 per thread.
// Both operands staged k-major in smem; float4 LDS in inner loop.
__global__ __launch_bounds__(256) void gemm64_kernel(
    const float* __restrict__ Xext, const float* __restrict__ W,
    int inSel, int outSel, int n)
{
    __shared__ float Xs[C * C];   // Xs[k*64 + r]  (transposed X tile)
    __shared__ float Ws[C * C];   // Ws[k*64 + c]  (W is [Cin][Cout] = already k-major)
    const float* X = inSel ? g_h : Xext;
    float* Y = (outSel == 0) ? g_hw : ((outSel == 1) ? g_A : g_B);

    int tid = threadIdx.x;
    int row0 = blockIdx.x * 64;

    for (int i = tid; i < C * C; i += 256) Ws[i] = W[i];
    // Load X tile, transposing: each thread loads one float4 (r, k4..k4+3)
    for (int i = tid; i < 64 * 16; i += 256) {
        int r = i >> 4;
        int k4 = (i & 15) * 4;
        int gr = row0 + r;
        float4 v = (gr < n) ? *(const float4*)(X + (size_t)gr * C + k4)
                            : make_float4(0.f, 0.f, 0.f, 0.f);
        Xs[(k4 + 0) * C + r] = v.x;
        Xs[(k4 + 1) * C + r] = v.y;
        Xs[(k4 + 2) * C + r] = v.z;
        Xs[(k4 + 3) * C + r] = v.w;
    }
    __syncthreads();

    int tx = tid & 15, ty = tid >> 4;
    float acc[4][4] = {};
    const float* xp = Xs + ty * 4;
    const float* wp = Ws + tx * 4;
    #pragma unroll 16
    for (int k = 0; k < C; k++) {
        float4 xa = *(const float4*)(xp + k * C);
        float4 wb = *(const float4*)(wp + k * C);
        acc[0][0] += xa.x * wb.x; acc[0][1] += xa.x * wb.y; acc[0][2] += xa.x * wb.z; acc[0][3] += xa.x * wb.w;
        acc[1][0] += xa.y * wb.x; acc[1][1] += xa.y * wb.y; acc[1][2] += xa.y * wb.z; acc[1][3] += xa.y * wb.w;
        acc[2][0] += xa.z * wb.x; acc[2][1] += xa.z * wb.y; acc[2][2] += xa.z * wb.z; acc[2][3] += xa.z * wb.w;
        acc[3][0] += xa.w * wb.x; acc[3][1] += xa.w * wb.y; acc[3][2] += xa.w * wb.z; acc[3][3] += xa.w * wb.w;
    }
    #pragma unroll
    for (int i = 0; i < 4; i++) {
        int r = row0 + ty * 4 + i;
        if (r < n)
            *(float4*)(Y + (size_t)r * C + tx * 4) =
                make_float4(acc[i][0], acc[i][1], acc[i][2], acc[i][3]);
    }
}

// ---------------- per-node: al/ar dots + self-loop init ----------------
__global__ __launch_bounds__(256) void self_kernel(
    const float* __restrict__ attL, const float* __restrict__ attR, int n)
{
    int node = (blockIdx.x * blockDim.x + threadIdx.x) >> 4;
    int lane = threadIdx.x & 15;
    if (node >= n) return;
    float4 h = ((const float4*)(g_hw + (size_t)node * C))[lane];
    float4 aL = ((const float4*)attL)[lane];
    float4 aR = ((const float4*)attR)[lane];
    float dl = h.x * aL.x + h.y * aL.y + h.z * aL.z + h.w * aL.w;
    float dr = h.x * aR.x + h.y * aR.y + h.z * aR.z + h.w * aR.w;
    float dd = h.x * h.x + h.y * h.y + h.z * h.z + h.w * h.w;
    #pragma unroll
    for (int o = 8; o; o >>= 1) {
        dl += __shfl_xor_sync(0xffffffffu, dl, o);
        dr += __shfl_xor_sync(0xffffffffu, dr, o);
        dd += __shfl_xor_sync(0xffffffffu, dd, o);
    }
    float a = (dl + dr) / (1.f + __expf(-dd));
    a = (a > 0.f) ? a : 0.2f * a;
    float ex = __expf(a);
    if (lane == 0) { g_al[node] = dl; g_ar[node] = dr; g_s[node] = ex; }
    ((float4*)(g_acc + (size_t)node * C))[lane] =
        make_float4(h.x * ex, h.y * ex, h.z * ex, h.w * ex);
}

// ---------------- fused attention + aggregation edge pass ----------------
// 16 lanes per edge, float4 gathers, vector red.v4 atomics.
__global__ __launch_bounds__(256) void edge_kernel(int E)
{
    int e = (blockIdx.x * blockDim.x + threadIdx.x) >> 4;
    int lane = threadIdx.x & 15;
    if (e >= E) return;
    int j = __ldg(g_src + e);
    int i = __ldg(g_dst + e);
    float4 hj = ((const float4*)(g_hw + (size_t)j * C))[lane];
    float4 hi = ((const float4*)(g_hw + (size_t)i * C))[lane];
    float d = hj.x * hi.x + hj.y * hi.y + hj.z * hi.z + hj.w * hi.w;
    #pragma unroll
    for (int o = 8; o; o >>= 1) d += __shfl_xor_sync(0xffffffffu, d, o);
    float a = (__ldg(g_al + j) + __ldg(g_ar + i)) / (1.f + __expf(-d));
    a = (a > 0.f) ? a : 0.2f * a;
    float ex = __expf(a);
    float* ap = g_acc + (size_t)i * C + lane * 4;
    asm volatile("red.global.add.v4.f32 [%0], {%1,%2,%3,%4};"
                 :: "l"(ap), "f"(hj.x * ex), "f"(hj.y * ex),
                    "f"(hj.z * ex), "f"(hj.w * ex) : "memory");
    if (lane == 0)
        asm volatile("red.global.add.f32 [%0], %1;"
                     :: "l"(g_s + i), "f"(ex) : "memory");
}

// ---------------- normalize + bias + relu -> g_h ----------------
__global__ __launch_bounds__(256) void finalize_kernel(
    const float* __restrict__ bias, int n)
{
    int idx = blockIdx.x * blockDim.x + threadIdx.x;
    if (idx >= n * C) return;
    int node = idx >> 6, c = idx & 63;
    float v = g_acc[idx] / g_s[node] + __ldg(bias + c);
    g_h[idx] = (v > 0.f) ? v : 0.f;
}

// ---------------- edge MLP ----------------
__global__ __launch_bounds__(256) void mlp_edge_kernel(
    const float* __restrict__ edge_attr,
    const float* __restrict__ Wm1row64,
    const float* __restrict__ bm1,
    const float* __restrict__ Wm2,
    const float* __restrict__ bm2,
    float* __restrict__ out, int E)
{
    int e = (blockIdx.x * blockDim.x + threadIdx.x) >> 4;
    int lane = threadIdx.x & 15;
    if (e >= E) return;
    int j = __ldg(g_src + e);
    int i = __ldg(g_dst + e);
    float ea = __ldg(edge_attr + e);
    float4 a  = ((const float4*)(g_A + (size_t)j * C))[lane];
    float4 b  = ((const float4*)(g_B + (size_t)i * C))[lane];
    float4 we = ((const float4*)Wm1row64)[lane];
    float4 bb = ((const float4*)bm1)[lane];
    float4 w2 = ((const float4*)Wm2)[lane];
    float tx = a.x + b.x + ea * we.x + bb.x; tx = (tx > 0.f) ? tx : 0.f;
    float ty = a.y + b.y + ea * we.y + bb.y; ty = (ty > 0.f) ? ty : 0.f;
    float tz = a.z + b.z + ea * we.z + bb.z; tz = (tz > 0.f) ? tz : 0.f;
    float tw = a.w + b.w + ea * we.w + bb.w; tw = (tw > 0.f) ? tw : 0.f;
    float d = tx * w2.x + ty * w2.y + tz * w2.z + tw * w2.w;
    #pragma unroll
    for (int o = 8; o; o >>= 1) d += __shfl_xor_sync(0xffffffffu, d, o);
    if (lane == 0) out[e] = d + __ldg(bm2);
}

// ---------------- launcher ----------------
extern "C" void kernel_launch(void* const* d_in, const int* in_sizes, int n_in,
                              void* d_out, int out_size)
{
    const float* x     = (const float*)d_in[0];
    const void*  ei    = d_in[1];
    const float* ea    = (const float*)d_in[2];
    const float* W1    = (const float*)d_in[3];
    const float* attL1 = (const float*)d_in[4];
    const float* attR1 = (const float*)d_in[5];
    const float* b1    = (const float*)d_in[6];
    const float* W2    = (const float*)d_in[7];
    const float* attL2 = (const float*)d_in[8];
    const float* attR2 = (const float*)d_in[9];
    const float* b2    = (const float*)d_in[10];
    const float* Wm1   = (const float*)d_in[11];
    const float* bm1   = (const float*)d_in[12];
    const float* Wm2   = (const float*)d_in[13];
    const float* bm2   = (const float*)d_in[14];
    float* out = (float*)d_out;

    int n = in_sizes[0] / C;
    int E = in_sizes[2];

    const int TB = 256;
    int gemmGrid   = (n + 63) / 64;
    int nodeGroups = (n * 16 + TB - 1) / TB;
    int edgeGroups = (int)(((size_t)E * 16 + TB - 1) / TB);
    int finGrid    = (n * C + TB - 1) / TB;

    reset_flag_kernel<<<1, 1>>>();
    detect_kernel<<<(E + TB - 1) / TB, TB>>>((const int*)ei, E);
    conv_idx_kernel<<<(E + TB - 1) / TB, TB>>>(ei, E);

    // ---- Layer 1 ----
    gemm64_kernel<<<gemmGrid, TB>>>(x, W1, 0, 0, n);
    self_kernel<<<nodeGroups, TB>>>(attL1, attR1, n);
    edge_kernel<<<edgeGroups, TB>>>(E);
    finalize_kernel<<<finGrid, TB>>>(b1, n);

    // ---- Layer 2 ----
    gemm64_kernel<<<gemmGrid, TB>>>(nullptr, W2, 1, 0, n);
    self_kernel<<<nodeGroups, TB>>>(attL2, attR2, n);
    edge_kernel<<<edgeGroups, TB>>>(E);
    finalize_kernel<<<finGrid, TB>>>(b2, n);

    // ---- Edge MLP ----
    gemm64_kernel<<<gemmGrid, TB>>>(nullptr, Wm1, 1, 1, n);          // A = h2 @ Wm1[0:64]
    gemm64_kernel<<<gemmGrid, TB>>>(nullptr, Wm1 + 65 * C, 1, 2, n); // B = h2 @ Wm1[65:129]
    mlp_edge_kernel<<<edgeGroups, TB>>>(ea, Wm1 + 64 * C, bm1, Wm2, bm2, out, E);
}